// round 2
// baseline (speedup 1.0000x reference)
#include <cuda_runtime.h>
#include <cstdint>

// Problem constants (fixed shapes per reference)
#define NN 50000
#define EE 800000
#define IN_F 128
#define KTOP 32

// Scratch (static device globals: allocation-free)
__device__ int   g_deg[NN];
__device__ int   g_rowptr[NN + 1];
__device__ int   g_cursor[NN];
__device__ int   g_csrc[EE];
__device__ float g_agg[(size_t)NN * IN_F];   // 25.6 MB (fully written by k_agg)

// ---------------------------------------------------------------------------
// Kernel 1: zero deg
// ---------------------------------------------------------------------------
__global__ void k_zero_deg() {
    int i = blockIdx.x * blockDim.x + threadIdx.x;
    if (i < NN) g_deg[i] = 0;
}

// ---------------------------------------------------------------------------
// Kernel 2: in-degree histogram over dst
// ---------------------------------------------------------------------------
__global__ void k_deg(const int* __restrict__ dst) {
    int i = blockIdx.x * blockDim.x + threadIdx.x;
    if (i < EE) atomicAdd(&g_deg[dst[i]], 1);
}

// ---------------------------------------------------------------------------
// Kernel 3: single-block exclusive prefix scan of deg -> rowptr (+cursor copy)
// 1024 threads, 49 elements each (1024*49 = 50176 >= NN).
// ---------------------------------------------------------------------------
#define SCAN_T 1024
#define SCAN_CH 49

__global__ __launch_bounds__(SCAN_T)
void k_scan() {
    __shared__ int sums[SCAN_T];
    int t = threadIdx.x;
    int base = t * SCAN_CH;

    int s = 0;
    #pragma unroll 7
    for (int i = 0; i < SCAN_CH; i++) {
        int j = base + i;
        if (j < NN) s += g_deg[j];
    }
    sums[t] = s;
    __syncthreads();

    // Hillis-Steele inclusive scan over per-thread totals
    for (int off = 1; off < SCAN_T; off <<= 1) {
        int tmp = 0;
        if (t >= off) tmp = sums[t - off];
        __syncthreads();
        if (t >= off) sums[t] += tmp;
        __syncthreads();
    }
    int run = sums[t] - s;   // exclusive prefix for this thread's chunk

    #pragma unroll 7
    for (int i = 0; i < SCAN_CH; i++) {
        int j = base + i;
        if (j < NN) {
            g_rowptr[j] = run;
            g_cursor[j] = run;
            run += g_deg[j];
        }
    }
    if (t == 0) g_rowptr[NN] = EE;
}

// ---------------------------------------------------------------------------
// Kernel 4: fill CSR src lists (order within a node is arbitrary; aggregation
// is a sum so result is order-independent up to fp rounding).
// ---------------------------------------------------------------------------
__global__ void k_fill(const int* __restrict__ src, const int* __restrict__ dst) {
    int i = blockIdx.x * blockDim.x + threadIdx.x;
    if (i < EE) {
        int d = dst[i];
        int pos = atomicAdd(&g_cursor[d], 1);
        g_csrc[pos] = src[i];
    }
}

// ---------------------------------------------------------------------------
// Kernel 5: gather aggregation. One warp per dst node; warp-private 128-float
// accumulator in smem (no atomics: within one edge the keep-mask makes lane
// writes address-disjoint; across edges the warp is serialized by __syncwarp).
// Duplicate topk indices within a row: reference .set() = last write wins ->
// keep only the HIGHEST lane among equal indices (match_any + clz).
// ---------------------------------------------------------------------------
__global__ __launch_bounds__(256)
void k_agg(const float* __restrict__ topk_values,
           const int*   __restrict__ topk_indices) {
    __shared__ float acc[8][IN_F];
    int w    = threadIdx.x >> 5;
    int lane = threadIdx.x & 31;
    int node = blockIdx.x * 8 + w;
    if (node >= NN) return;

    float* a = acc[w];
    a[lane]      = 0.f;
    a[lane + 32] = 0.f;
    a[lane + 64] = 0.f;
    a[lane + 96] = 0.f;
    __syncwarp();

    int beg = g_rowptr[node];
    int end = g_rowptr[node + 1];

    for (int e = beg; e < end; e++) {
        int s = g_csrc[e];                              // broadcast load
        float v  = topk_values[(size_t)s * KTOP + lane]; // coalesced 128B
        int   ix = topk_indices[(size_t)s * KTOP + lane];
        unsigned peers = __match_any_sync(0xffffffffu, ix);
        if (lane == (31 - __clz(peers)))                 // last-wins dedup
            a[ix] += v;
        __syncwarp();
    }

    float winv = 1.0f / fmaxf((float)(end - beg), 1.0f);
    float4 r;
    r.x = a[lane * 4 + 0] * winv;
    r.y = a[lane * 4 + 1] * winv;
    r.z = a[lane * 4 + 2] * winv;
    r.w = a[lane * 4 + 3] * winv;
    *reinterpret_cast<float4*>(g_agg + (size_t)node * IN_F + lane * 4) = r;
}

// ---------------------------------------------------------------------------
// Kernel 6: fused GEMM  out = [feat | agg] @ [W_self ; W_neigh] + b_self
// M = NN, N = 128, K = 256.  128x128 tile, BK=16, 8x8 per thread, 256 thr.
// ---------------------------------------------------------------------------
#define BM 128
#define BN 128
#define BK 16

__global__ __launch_bounds__(256, 2)
void k_gemm(const float* __restrict__ feat,
            const float* __restrict__ Wself,
            const float* __restrict__ bself,
            const float* __restrict__ Wneigh,
            float* __restrict__ out) {
    __shared__ float As[BK][BM + 4];
    __shared__ float Bs[BK][BN];

    const int t  = threadIdx.x;
    const int m0 = blockIdx.x * BM;
    const int tx = t & 15;     // 0..15 -> output cols tx*8..
    const int ty = t >> 4;     // 0..15 -> output rows ty*8..

    float acc[8][8];
    #pragma unroll
    for (int i = 0; i < 8; i++)
        #pragma unroll
        for (int j = 0; j < 8; j++) acc[i][j] = 0.f;

    for (int kc = 0; kc < 256; kc += BK) {
        const float* Asrc = (kc < 128) ? feat   : g_agg;
        const float* Bsrc = (kc < 128) ? Wself  : Wneigh;
        const int kbase = kc & 127;

        // Load A tile: 128 rows x 16 k = 512 float4, 2 per thread; store
        // transposed As[k][m] so compute reads are contiguous over m.
        #pragma unroll
        for (int l = 0; l < 2; l++) {
            int f4  = t + l * 256;
            int row = f4 >> 2;     // 0..127
            int kq  = f4 & 3;      // 0..3 (k quarter)
            int gr  = m0 + row;
            float4 v = make_float4(0.f, 0.f, 0.f, 0.f);
            if (gr < NN)
                v = *reinterpret_cast<const float4*>(
                        Asrc + (size_t)gr * IN_F + kbase + kq * 4);
            As[kq * 4 + 0][row] = v.x;
            As[kq * 4 + 1][row] = v.y;
            As[kq * 4 + 2][row] = v.z;
            As[kq * 4 + 3][row] = v.w;
        }

        // Load B tile: 16 k x 128 n = 512 float4, 2 per thread.
        #pragma unroll
        for (int l = 0; l < 2; l++) {
            int f4 = t + l * 256;
            int kr = f4 >> 5;      // 0..15
            int nq = f4 & 31;      // 0..31
            float4 v = *reinterpret_cast<const float4*>(
                           Bsrc + (size_t)(kbase + kr) * 128 + nq * 4);
            *reinterpret_cast<float4*>(&Bs[kr][nq * 4]) = v;
        }
        __syncthreads();

        #pragma unroll
        for (int kk = 0; kk < BK; kk++) {
            float a[8], b[8];
            #pragma unroll
            for (int i = 0; i < 8; i++) a[i] = As[kk][ty * 8 + i];
            #pragma unroll
            for (int j = 0; j < 8; j++) b[j] = Bs[kk][tx * 8 + j];
            #pragma unroll
            for (int i = 0; i < 8; i++)
                #pragma unroll
                for (int j = 0; j < 8; j++)
                    acc[i][j] = fmaf(a[i], b[j], acc[i][j]);
        }
        __syncthreads();
    }

    // Epilogue: add bias, store
    #pragma unroll
    for (int i = 0; i < 8; i++) {
        int gr = m0 + ty * 8 + i;
        if (gr < NN) {
            #pragma unroll
            for (int j = 0; j < 8; j += 4) {
                int c = tx * 8 + j;
                float4 v;
                v.x = acc[i][j + 0] + bself[c + 0];
                v.y = acc[i][j + 1] + bself[c + 1];
                v.z = acc[i][j + 2] + bself[c + 2];
                v.w = acc[i][j + 3] + bself[c + 3];
                *reinterpret_cast<float4*>(out + (size_t)gr * IN_F + c) = v;
            }
        }
    }
}

// ---------------------------------------------------------------------------
// Launch
// inputs: feat, topk_values, topk_indices, src, dst, W_self, b_self, W_neigh
// ---------------------------------------------------------------------------
extern "C" void kernel_launch(void* const* d_in, const int* in_sizes, int n_in,
                              void* d_out, int out_size) {
    const float* feat   = (const float*)d_in[0];
    const float* tkv    = (const float*)d_in[1];
    const int*   tki    = (const int*)  d_in[2];
    const int*   src    = (const int*)  d_in[3];
    const int*   dst    = (const int*)  d_in[4];
    const float* Wself  = (const float*)d_in[5];
    const float* bself  = (const float*)d_in[6];
    const float* Wneigh = (const float*)d_in[7];
    float* out = (float*)d_out;

    k_zero_deg<<<(NN + 255) / 256, 256>>>();
    k_deg<<<(EE + 255) / 256, 256>>>(dst);
    k_scan<<<1, SCAN_T>>>();
    k_fill<<<(EE + 255) / 256, 256>>>(src, dst);
    k_agg<<<(NN + 7) / 8, 256>>>(tkv, tki);
    k_gemm<<<(NN + BM - 1) / BM, 256>>>(feat, Wself, bself, Wneigh, out);
}

// round 4
// speedup vs baseline: 1.4732x; 1.4732x over previous
#include <cuda_runtime.h>
#include <cstdint>

// Problem constants (fixed shapes per reference)
#define NN 50000
#define EE 800000
#define IN_F 128
#define KTOP 32

// Scratch (static device globals: allocation-free)
__device__ int   g_deg[NN];
__device__ int   g_rowptr[NN + 1];
__device__ int   g_cursor[NN];
__device__ int   g_csrc[EE];
__device__ float g_y[(size_t)NN * IN_F];       // y = x_sparse @ W_neigh
__device__ float g_hneigh[(size_t)NN * IN_F];  // edge-averaged y

// ---------------------------------------------------------------------------
// Kernel 1: zero deg
// ---------------------------------------------------------------------------
__global__ void k_zero_deg() {
    int i = blockIdx.x * blockDim.x + threadIdx.x;
    if (i < NN) g_deg[i] = 0;
}

// ---------------------------------------------------------------------------
// Kernel 2: in-degree histogram over dst
// ---------------------------------------------------------------------------
__global__ void k_deg(const int* __restrict__ dst) {
    int i = blockIdx.x * blockDim.x + threadIdx.x;
    if (i < EE) atomicAdd(&g_deg[dst[i]], 1);
}

// ---------------------------------------------------------------------------
// Kernel 3: single-block exclusive prefix scan of deg -> rowptr (+cursor copy)
// ---------------------------------------------------------------------------
#define SCAN_T 1024
#define SCAN_CH 49

__global__ __launch_bounds__(SCAN_T)
void k_scan() {
    __shared__ int sums[SCAN_T];
    int t = threadIdx.x;
    int base = t * SCAN_CH;

    int s = 0;
    #pragma unroll 7
    for (int i = 0; i < SCAN_CH; i++) {
        int j = base + i;
        if (j < NN) s += g_deg[j];
    }
    sums[t] = s;
    __syncthreads();

    for (int off = 1; off < SCAN_T; off <<= 1) {
        int tmp = 0;
        if (t >= off) tmp = sums[t - off];
        __syncthreads();
        if (t >= off) sums[t] += tmp;
        __syncthreads();
    }
    int run = sums[t] - s;

    #pragma unroll 7
    for (int i = 0; i < SCAN_CH; i++) {
        int j = base + i;
        if (j < NN) {
            g_rowptr[j] = run;
            g_cursor[j] = run;
            run += g_deg[j];
        }
    }
    if (t == 0) g_rowptr[NN] = EE;
}

// ---------------------------------------------------------------------------
// Kernel 4: fill CSR src lists (order within node arbitrary; sum is
// order-independent up to fp rounding).
// ---------------------------------------------------------------------------
__global__ void k_fill(const int* __restrict__ src, const int* __restrict__ dst) {
    int i = blockIdx.x * blockDim.x + threadIdx.x;
    if (i < EE) {
        int d = dst[i];
        int pos = atomicAdd(&g_cursor[d], 1);
        g_csrc[pos] = src[i];
    }
}

// ---------------------------------------------------------------------------
// Kernel 5: y[s] = x_sparse[s] @ W_neigh  (sparse rows x dense weight)
// Grid (GX, 2): blockIdx.y selects a 64-col half of W_neigh held in smem.
// One warp per node (grid-stride). Dedup (reference .set() last-wins):
// highest lane among equal indices keeps its value, others zeroed.
// ---------------------------------------------------------------------------
#define SGX 296

__global__ __launch_bounds__(256)
void k_sparse_gemm(const float* __restrict__ topk_values,
                   const int*   __restrict__ topk_indices,
                   const float* __restrict__ Wneigh) {
    __shared__ float Wn[IN_F][64];
    const int t    = threadIdx.x;
    const int w    = t >> 5;
    const int lane = t & 31;
    const int h    = blockIdx.y;          // 0 or 1: which 64-col half
    const int c0   = h * 64;

    // Load W_neigh[:, c0:c0+64] into smem: 8192 floats, 32 per thread.
    #pragma unroll
    for (int l = 0; l < 8; l++) {
        int idx  = t + l * 256;           // float4 index, 0..2047
        int row  = idx >> 4;              // /16
        int col4 = idx & 15;
        *reinterpret_cast<float4*>(&Wn[row][col4 * 4]) =
            *reinterpret_cast<const float4*>(Wneigh + (size_t)row * IN_F + c0 + col4 * 4);
    }
    __syncthreads();

    for (int node = blockIdx.x * 8 + w; node < NN; node += SGX * 8) {
        float v  = topk_values[(size_t)node * KTOP + lane];
        int   ix = topk_indices[(size_t)node * KTOP + lane];
        unsigned peers = __match_any_sync(0xffffffffu, ix);
        if (lane != (31 - __clz(peers))) v = 0.f;   // last-wins dedup

        float2 acc = make_float2(0.f, 0.f);
        #pragma unroll
        for (int k = 0; k < KTOP; k++) {
            float vk = __shfl_sync(0xffffffffu, v, k);
            int   ik = __shfl_sync(0xffffffffu, ix, k);
            if (vk != 0.f) {
                float2 wv = *reinterpret_cast<const float2*>(&Wn[ik][lane * 2]);
                acc.x = fmaf(vk, wv.x, acc.x);
                acc.y = fmaf(vk, wv.y, acc.y);
            }
        }
        *reinterpret_cast<float2*>(g_y + (size_t)node * IN_F + c0 + lane * 2) = acc;
    }
}

// ---------------------------------------------------------------------------
// Kernel 6: h_neigh[d] = (1/max(deg,1)) * sum_{e: dst=d} y[src_e]
// One warp per dst node; each lane owns 4 cols (float4). Coalesced 512B row
// reads of L2-resident y; 4-edge unroll for MLP.
// ---------------------------------------------------------------------------
__global__ __launch_bounds__(256)
void k_gather() {
    const int w    = threadIdx.x >> 5;
    const int lane = threadIdx.x & 31;
    const int node = blockIdx.x * 8 + w;
    if (node >= NN) return;

    const int beg = g_rowptr[node];
    const int end = g_rowptr[node + 1];
    const float4* y4 = reinterpret_cast<const float4*>(g_y);

    float4 a0 = make_float4(0.f, 0.f, 0.f, 0.f);
    float4 a1 = make_float4(0.f, 0.f, 0.f, 0.f);
    float4 a2 = make_float4(0.f, 0.f, 0.f, 0.f);
    float4 a3 = make_float4(0.f, 0.f, 0.f, 0.f);

    int e = beg;
    for (; e + 3 < end; e += 4) {
        int s0 = g_csrc[e + 0];
        int s1 = g_csrc[e + 1];
        int s2 = g_csrc[e + 2];
        int s3 = g_csrc[e + 3];
        float4 v0 = y4[(size_t)s0 * 32 + lane];
        float4 v1 = y4[(size_t)s1 * 32 + lane];
        float4 v2 = y4[(size_t)s2 * 32 + lane];
        float4 v3 = y4[(size_t)s3 * 32 + lane];
        a0.x += v0.x; a0.y += v0.y; a0.z += v0.z; a0.w += v0.w;
        a1.x += v1.x; a1.y += v1.y; a1.z += v1.z; a1.w += v1.w;
        a2.x += v2.x; a2.y += v2.y; a2.z += v2.z; a2.w += v2.w;
        a3.x += v3.x; a3.y += v3.y; a3.z += v3.z; a3.w += v3.w;
    }
    for (; e < end; e++) {
        int s0 = g_csrc[e];
        float4 v0 = y4[(size_t)s0 * 32 + lane];
        a0.x += v0.x; a0.y += v0.y; a0.z += v0.z; a0.w += v0.w;
    }

    float winv = 1.0f / fmaxf((float)(end - beg), 1.0f);
    float4 r;
    r.x = (a0.x + a1.x + a2.x + a3.x) * winv;
    r.y = (a0.y + a1.y + a2.y + a3.y) * winv;
    r.z = (a0.z + a1.z + a2.z + a3.z) * winv;
    r.w = (a0.w + a1.w + a2.w + a3.w) * winv;
    *reinterpret_cast<float4*>(g_hneigh + (size_t)node * IN_F + lane * 4) = r;
}

// ---------------------------------------------------------------------------
// Kernel 7: out = feat @ W_self + b_self + h_neigh   (M=NN, N=128, K=128)
// 128x128 tile, BK=16, 8x8 per thread, 256 threads.
// ---------------------------------------------------------------------------
#define BM 128
#define BN 128
#define BK 16

__global__ __launch_bounds__(256, 2)
void k_gemm(const float* __restrict__ feat,
            const float* __restrict__ Wself,
            const float* __restrict__ bself,
            float* __restrict__ out) {
    __shared__ float As[BK][BM + 4];
    __shared__ float Bs[BK][BN];

    const int t  = threadIdx.x;
    const int m0 = blockIdx.x * BM;
    const int tx = t & 15;
    const int ty = t >> 4;

    float acc[8][8];
    #pragma unroll
    for (int i = 0; i < 8; i++)
        #pragma unroll
        for (int j = 0; j < 8; j++) acc[i][j] = 0.f;

    for (int kc = 0; kc < IN_F; kc += BK) {
        #pragma unroll
        for (int l = 0; l < 2; l++) {
            int f4  = t + l * 256;
            int row = f4 >> 2;
            int kq  = f4 & 3;
            int gr  = m0 + row;
            float4 v = make_float4(0.f, 0.f, 0.f, 0.f);
            if (gr < NN)
                v = *reinterpret_cast<const float4*>(
                        feat + (size_t)gr * IN_F + kc + kq * 4);
            As[kq * 4 + 0][row] = v.x;
            As[kq * 4 + 1][row] = v.y;
            As[kq * 4 + 2][row] = v.z;
            As[kq * 4 + 3][row] = v.w;
        }
        #pragma unroll
        for (int l = 0; l < 2; l++) {
            int f4 = t + l * 256;
            int kr = f4 >> 5;
            int nq = f4 & 31;
            float4 v = *reinterpret_cast<const float4*>(
                           Wself + (size_t)(kc + kr) * 128 + nq * 4);
            *reinterpret_cast<float4*>(&Bs[kr][nq * 4]) = v;
        }
        __syncthreads();

        #pragma unroll
        for (int kk = 0; kk < BK; kk++) {
            float a[8], b[8];
            #pragma unroll
            for (int i = 0; i < 8; i++) a[i] = As[kk][ty * 8 + i];
            #pragma unroll
            for (int j = 0; j < 8; j++) b[j] = Bs[kk][tx * 8 + j];
            #pragma unroll
            for (int i = 0; i < 8; i++)
                #pragma unroll
                for (int j = 0; j < 8; j++)
                    acc[i][j] = fmaf(a[i], b[j], acc[i][j]);
        }
        __syncthreads();
    }

    #pragma unroll
    for (int i = 0; i < 8; i++) {
        int gr = m0 + ty * 8 + i;
        if (gr < NN) {
            #pragma unroll
            for (int j = 0; j < 8; j += 4) {
                int c = tx * 8 + j;
                float4 hn = *reinterpret_cast<const float4*>(
                                g_hneigh + (size_t)gr * IN_F + c);
                float4 v;
                v.x = acc[i][j + 0] + bself[c + 0] + hn.x;
                v.y = acc[i][j + 1] + bself[c + 1] + hn.y;
                v.z = acc[i][j + 2] + bself[c + 2] + hn.z;
                v.w = acc[i][j + 3] + bself[c + 3] + hn.w;
                *reinterpret_cast<float4*>(out + (size_t)gr * IN_F + c) = v;
            }
        }
    }
}

// ---------------------------------------------------------------------------
// Launch
// inputs: feat, topk_values, topk_indices, src, dst, W_self, b_self, W_neigh
// ---------------------------------------------------------------------------
extern "C" void kernel_launch(void* const* d_in, const int* in_sizes, int n_in,
                              void* d_out, int out_size) {
    const float* feat   = (const float*)d_in[0];
    const float* tkv    = (const float*)d_in[1];
    const int*   tki    = (const int*)  d_in[2];
    const int*   src    = (const int*)  d_in[3];
    const int*   dst    = (const int*)  d_in[4];
    const float* Wself  = (const float*)d_in[5];
    const float* bself  = (const float*)d_in[6];
    const float* Wneigh = (const float*)d_in[7];
    float* out = (float*)d_out;

    k_zero_deg<<<(NN + 255) / 256, 256>>>();
    k_deg<<<(EE + 255) / 256, 256>>>(dst);
    k_scan<<<1, SCAN_T>>>();
    k_fill<<<(EE + 255) / 256, 256>>>(src, dst);
    k_sparse_gemm<<<dim3(SGX, 2), 256>>>(tkv, tki, Wneigh);
    k_gather<<<(NN + 7) / 8, 256>>>();
    k_gemm<<<(NN + BM - 1) / BM, 256>>>(feat, Wself, bself, out);
}

// round 5
// speedup vs baseline: 1.9354x; 1.3138x over previous
#include <cuda_runtime.h>
#include <cstdint>

// Problem constants (fixed shapes per reference)
#define NN 50000
#define EE 800000
#define IN_F 128
#define KTOP 32

// Scratch (static device globals: allocation-free)
__device__ int   g_deg[NN];
__device__ int   g_rowptr[NN + 1];
__device__ int   g_cursor[NN];
__device__ int   g_csrc[EE];
__device__ float g_y[(size_t)NN * IN_F];       // y = x_sparse @ W_neigh

// ---------------------------------------------------------------------------
// Kernel 1: zero deg
// ---------------------------------------------------------------------------
__global__ void k_zero_deg() {
    int i = blockIdx.x * blockDim.x + threadIdx.x;
    if (i < NN) g_deg[i] = 0;
}

// ---------------------------------------------------------------------------
// Kernel 2: in-degree histogram over dst (4 edges/thread, vectorized load)
// ---------------------------------------------------------------------------
__global__ void k_deg(const int* __restrict__ dst) {
    int i = blockIdx.x * blockDim.x + threadIdx.x;   // int4 index
    if (i * 4 + 3 < EE) {
        int4 d = reinterpret_cast<const int4*>(dst)[i];
        atomicAdd(&g_deg[d.x], 1);
        atomicAdd(&g_deg[d.y], 1);
        atomicAdd(&g_deg[d.z], 1);
        atomicAdd(&g_deg[d.w], 1);
    } else {
        for (int j = i * 4; j < EE; j++) atomicAdd(&g_deg[dst[j]], 1);
    }
}

// ---------------------------------------------------------------------------
// Kernel 3: single-block exclusive prefix scan of deg -> rowptr (+cursor copy)
// ---------------------------------------------------------------------------
#define SCAN_T 1024
#define SCAN_CH 49

__global__ __launch_bounds__(SCAN_T)
void k_scan() {
    __shared__ int sums[SCAN_T];
    int t = threadIdx.x;
    int base = t * SCAN_CH;

    int s = 0;
    #pragma unroll 7
    for (int i = 0; i < SCAN_CH; i++) {
        int j = base + i;
        if (j < NN) s += g_deg[j];
    }
    sums[t] = s;
    __syncthreads();

    for (int off = 1; off < SCAN_T; off <<= 1) {
        int tmp = 0;
        if (t >= off) tmp = sums[t - off];
        __syncthreads();
        if (t >= off) sums[t] += tmp;
        __syncthreads();
    }
    int run = sums[t] - s;

    #pragma unroll 7
    for (int i = 0; i < SCAN_CH; i++) {
        int j = base + i;
        if (j < NN) {
            g_rowptr[j] = run;
            g_cursor[j] = run;
            run += g_deg[j];
        }
    }
    if (t == 0) g_rowptr[NN] = EE;
}

// ---------------------------------------------------------------------------
// Kernel 4: fill CSR src lists (order within node arbitrary; sum is
// order-independent up to fp rounding). 2 edges/thread.
// ---------------------------------------------------------------------------
__global__ void k_fill(const int* __restrict__ src, const int* __restrict__ dst) {
    int i = blockIdx.x * blockDim.x + threadIdx.x;   // int2 index
    if (i * 2 + 1 < EE) {
        int2 d = reinterpret_cast<const int2*>(dst)[i];
        int2 s = reinterpret_cast<const int2*>(src)[i];
        int p0 = atomicAdd(&g_cursor[d.x], 1);
        int p1 = atomicAdd(&g_cursor[d.y], 1);
        g_csrc[p0] = s.x;
        g_csrc[p1] = s.y;
    } else {
        for (int j = i * 2; j < EE; j++) {
            int pos = atomicAdd(&g_cursor[dst[j]], 1);
            g_csrc[pos] = src[j];
        }
    }
}

// ---------------------------------------------------------------------------
// Kernel 5: y[s] = x_sparse[s] @ W_neigh  (sparse rows x dense weight)
// Grid (SGX, 2): blockIdx.y selects a 64-col half of W_neigh held in smem.
// One warp per node (grid-stride). Dedup (reference .set() last-wins):
// highest lane among equal indices keeps its value, others zeroed.
// ---------------------------------------------------------------------------
#define SGX 296

__global__ __launch_bounds__(256)
void k_sparse_gemm(const float* __restrict__ topk_values,
                   const int*   __restrict__ topk_indices,
                   const float* __restrict__ Wneigh) {
    __shared__ float Wn[IN_F][64];
    const int t    = threadIdx.x;
    const int w    = t >> 5;
    const int lane = t & 31;
    const int c0   = blockIdx.y * 64;

    #pragma unroll
    for (int l = 0; l < 8; l++) {
        int idx  = t + l * 256;           // float4 index, 0..2047
        int row  = idx >> 4;
        int col4 = idx & 15;
        *reinterpret_cast<float4*>(&Wn[row][col4 * 4]) =
            *reinterpret_cast<const float4*>(Wneigh + (size_t)row * IN_F + c0 + col4 * 4);
    }
    __syncthreads();

    for (int node = blockIdx.x * 8 + w; node < NN; node += SGX * 8) {
        float v  = topk_values[(size_t)node * KTOP + lane];
        int   ix = topk_indices[(size_t)node * KTOP + lane];
        unsigned peers = __match_any_sync(0xffffffffu, ix);
        if (lane != (31 - __clz(peers))) v = 0.f;   // last-wins dedup

        float2 acc = make_float2(0.f, 0.f);
        #pragma unroll
        for (int k = 0; k < KTOP; k++) {
            float vk = __shfl_sync(0xffffffffu, v, k);
            int   ik = __shfl_sync(0xffffffffu, ix, k);
            if (vk != 0.f) {
                float2 wv = *reinterpret_cast<const float2*>(&Wn[ik][lane * 2]);
                acc.x = fmaf(vk, wv.x, acc.x);
                acc.y = fmaf(vk, wv.y, acc.y);
            }
        }
        *reinterpret_cast<float2*>(g_y + (size_t)node * IN_F + c0 + lane * 2) = acc;
    }
}

// ---------------------------------------------------------------------------
// Kernel 6: out[d] += (1/max(deg,1)) * sum_{e: dst=d} y[src_e]
// One warp per dst node; each lane owns 4 cols (float4). Coalesced 512B row
// reads of L2-resident y; 4-edge unroll for MLP. Non-atomic += into out
// (each row owned by exactly one warp; gemm_self wrote it first).
// ---------------------------------------------------------------------------
__global__ __launch_bounds__(256)
void k_gather_add(float* __restrict__ out) {
    const int w    = threadIdx.x >> 5;
    const int lane = threadIdx.x & 31;
    const int node = blockIdx.x * 8 + w;
    if (node >= NN) return;

    const int beg = g_rowptr[node];
    const int end = g_rowptr[node + 1];
    const float4* y4 = reinterpret_cast<const float4*>(g_y);

    float4 a0 = make_float4(0.f, 0.f, 0.f, 0.f);
    float4 a1 = make_float4(0.f, 0.f, 0.f, 0.f);
    float4 a2 = make_float4(0.f, 0.f, 0.f, 0.f);
    float4 a3 = make_float4(0.f, 0.f, 0.f, 0.f);

    int e = beg;
    for (; e + 3 < end; e += 4) {
        int s0 = g_csrc[e + 0];
        int s1 = g_csrc[e + 1];
        int s2 = g_csrc[e + 2];
        int s3 = g_csrc[e + 3];
        float4 v0 = y4[(size_t)s0 * 32 + lane];
        float4 v1 = y4[(size_t)s1 * 32 + lane];
        float4 v2 = y4[(size_t)s2 * 32 + lane];
        float4 v3 = y4[(size_t)s3 * 32 + lane];
        a0.x += v0.x; a0.y += v0.y; a0.z += v0.z; a0.w += v0.w;
        a1.x += v1.x; a1.y += v1.y; a1.z += v1.z; a1.w += v1.w;
        a2.x += v2.x; a2.y += v2.y; a2.z += v2.z; a2.w += v2.w;
        a3.x += v3.x; a3.y += v3.y; a3.z += v3.z; a3.w += v3.w;
    }
    for (; e < end; e++) {
        int s0 = g_csrc[e];
        float4 v0 = y4[(size_t)s0 * 32 + lane];
        a0.x += v0.x; a0.y += v0.y; a0.z += v0.z; a0.w += v0.w;
    }

    float winv = 1.0f / fmaxf((float)(end - beg), 1.0f);
    float* op = out + (size_t)node * IN_F + lane * 4;
    float4 cur = *reinterpret_cast<const float4*>(op);
    float4 r;
    r.x = cur.x + (a0.x + a1.x + a2.x + a3.x) * winv;
    r.y = cur.y + (a0.y + a1.y + a2.y + a3.y) * winv;
    r.z = cur.z + (a0.z + a1.z + a2.z + a3.z) * winv;
    r.w = cur.w + (a0.w + a1.w + a2.w + a3.w) * winv;
    *reinterpret_cast<float4*>(op) = r;
}

// ---------------------------------------------------------------------------
// Kernel 7: out = feat @ W_self + b_self   (M=NN, N=128, K=128)
// 128x128 tile, BK=16, 8x8 per thread, 256 threads.
// ---------------------------------------------------------------------------
#define BM 128
#define BN 128
#define BK 16

__global__ __launch_bounds__(256, 2)
void k_gemm_self(const float* __restrict__ feat,
                 const float* __restrict__ Wself,
                 const float* __restrict__ bself,
                 float* __restrict__ out) {
    __shared__ float As[BK][BM + 4];
    __shared__ float Bs[BK][BN];

    const int t  = threadIdx.x;
    const int m0 = blockIdx.x * BM;
    const int tx = t & 15;
    const int ty = t >> 4;

    float acc[8][8];
    #pragma unroll
    for (int i = 0; i < 8; i++)
        #pragma unroll
        for (int j = 0; j < 8; j++) acc[i][j] = 0.f;

    for (int kc = 0; kc < IN_F; kc += BK) {
        #pragma unroll
        for (int l = 0; l < 2; l++) {
            int f4  = t + l * 256;
            int row = f4 >> 2;
            int kq  = f4 & 3;
            int gr  = m0 + row;
            float4 v = make_float4(0.f, 0.f, 0.f, 0.f);
            if (gr < NN)
                v = *reinterpret_cast<const float4*>(
                        feat + (size_t)gr * IN_F + kc + kq * 4);
            As[kq * 4 + 0][row] = v.x;
            As[kq * 4 + 1][row] = v.y;
            As[kq * 4 + 2][row] = v.z;
            As[kq * 4 + 3][row] = v.w;
        }
        #pragma unroll
        for (int l = 0; l < 2; l++) {
            int f4 = t + l * 256;
            int kr = f4 >> 5;
            int nq = f4 & 31;
            float4 v = *reinterpret_cast<const float4*>(
                           Wself + (size_t)(kc + kr) * 128 + nq * 4);
            *reinterpret_cast<float4*>(&Bs[kr][nq * 4]) = v;
        }
        __syncthreads();

        #pragma unroll
        for (int kk = 0; kk < BK; kk++) {
            float a[8], b[8];
            #pragma unroll
            for (int i = 0; i < 8; i++) a[i] = As[kk][ty * 8 + i];
            #pragma unroll
            for (int j = 0; j < 8; j++) b[j] = Bs[kk][tx * 8 + j];
            #pragma unroll
            for (int i = 0; i < 8; i++)
                #pragma unroll
                for (int j = 0; j < 8; j++)
                    acc[i][j] = fmaf(a[i], b[j], acc[i][j]);
        }
        __syncthreads();
    }

    #pragma unroll
    for (int i = 0; i < 8; i++) {
        int gr = m0 + ty * 8 + i;
        if (gr < NN) {
            #pragma unroll
            for (int j = 0; j < 8; j += 4) {
                int c = tx * 8 + j;
                float4 v;
                v.x = acc[i][j + 0] + bself[c + 0];
                v.y = acc[i][j + 1] + bself[c + 1];
                v.z = acc[i][j + 2] + bself[c + 2];
                v.w = acc[i][j + 3] + bself[c + 3];
                *reinterpret_cast<float4*>(out + (size_t)gr * IN_F + c) = v;
            }
        }
    }
}

// ---------------------------------------------------------------------------
// Launch: 3-branch stream graph.
//   branch csr (s1):  zero -> deg -> scan -> fill
//   branch y   (s2):  sparse_gemm
//   main   (0):       gemm_self; then join csr+y; then gather_add
// Streams/events are created once (correctness call runs before capture),
// so no creation happens during graph capture. Every call records/waits
// identically -> deterministic.
// ---------------------------------------------------------------------------
extern "C" void kernel_launch(void* const* d_in, const int* in_sizes, int n_in,
                              void* d_out, int out_size) {
    const float* feat   = (const float*)d_in[0];
    const float* tkv    = (const float*)d_in[1];
    const int*   tki    = (const int*)  d_in[2];
    const int*   src    = (const int*)  d_in[3];
    const int*   dst    = (const int*)  d_in[4];
    const float* Wself  = (const float*)d_in[5];
    const float* bself  = (const float*)d_in[6];
    const float* Wneigh = (const float*)d_in[7];
    float* out = (float*)d_out;

    static cudaStream_t s1 = nullptr, s2 = nullptr;
    static cudaEvent_t evRoot = nullptr, evCsr = nullptr, evY = nullptr;
    if (s1 == nullptr) {
        cudaStreamCreateWithFlags(&s1, cudaStreamNonBlocking);
        cudaStreamCreateWithFlags(&s2, cudaStreamNonBlocking);
        cudaEventCreateWithFlags(&evRoot, cudaEventDisableTiming);
        cudaEventCreateWithFlags(&evCsr,  cudaEventDisableTiming);
        cudaEventCreateWithFlags(&evY,    cudaEventDisableTiming);
    }

    // Fork
    cudaEventRecord(evRoot, 0);
    cudaStreamWaitEvent(s1, evRoot, 0);
    cudaStreamWaitEvent(s2, evRoot, 0);

    // Branch: CSR build
    k_zero_deg<<<(NN + 255) / 256, 256, 0, s1>>>();
    k_deg<<<(EE / 4 + 255) / 256, 256, 0, s1>>>(dst);
    k_scan<<<1, SCAN_T, 0, s1>>>();
    k_fill<<<(EE / 2 + 255) / 256, 256, 0, s1>>>(src, dst);
    cudaEventRecord(evCsr, s1);

    // Branch: sparse gemm (y)
    k_sparse_gemm<<<dim3(SGX, 2), 256, 0, s2>>>(tkv, tki, Wneigh);
    cudaEventRecord(evY, s2);

    // Main: self gemm (longest branch)
    k_gemm_self<<<(NN + BM - 1) / BM, 256>>>(feat, Wself, bself, out);

    // Join, then gather+add
    cudaStreamWaitEvent(0, evCsr, 0);
    cudaStreamWaitEvent(0, evY, 0);
    k_gather_add<<<(NN + 7) / 8, 256>>>(out);
}